// round 16
// baseline (speedup 1.0000x reference)
#include <cuda_runtime.h>
#include <cuda_fp16.h>
#include <cstdint>

#define DM   1024
#define NH   16
#define DKH  64
#define BB   4
#define SS   2048
#define MROWS (BB*SS)   // 8192

// ---------------- device scratch (allocation-free rule) ----------------
__device__ __half g_x16[MROWS*DM];
__device__ __half g_w[4*DM*DM];
__device__ __half g_q[BB*NH*SS*DKH];   // pre-scaled by 1/8
__device__ __half g_k[BB*NH*SS*DKH];
__device__ __half g_v[BB*NH*SS*DKH];
__device__ __half g_ao[MROWS*DM];

// ---------------- PTX helpers (baseline ISA: sm_80-class) ----------------
__device__ __forceinline__ uint32_t smem_u32(const void* p) {
    uint32_t a;
    asm("{ .reg .u64 t; cvta.to.shared.u64 t, %1; cvt.u32.u64 %0, t; }" : "=r"(a) : "l"(p));
    return a;
}
__device__ __forceinline__ void cp16(uint32_t dst, const void* src) {
    asm volatile("cp.async.cg.shared.global [%0], [%1], 16;" :: "r"(dst), "l"(src));
}
__device__ __forceinline__ void cp_commit() {
    asm volatile("cp.async.commit_group;" ::: "memory");
}
template<int N> __device__ __forceinline__ void cp_wait() {
    asm volatile("cp.async.wait_group %0;" :: "n"(N) : "memory");
}
__device__ __forceinline__ void cp_wait_rem(int rem) {
    if (rem >= 2)      cp_wait<2>();
    else if (rem == 1) cp_wait<1>();
    else               cp_wait<0>();
}
__device__ __forceinline__ void ldsm_x4(uint32_t& r0, uint32_t& r1, uint32_t& r2, uint32_t& r3,
                                        uint32_t addr) {
    asm volatile("ldmatrix.sync.aligned.m8n8.x4.shared.b16 {%0,%1,%2,%3}, [%4];"
                 : "=r"(r0), "=r"(r1), "=r"(r2), "=r"(r3) : "r"(addr));
}
__device__ __forceinline__ void ldsm_x4t(uint32_t& r0, uint32_t& r1, uint32_t& r2, uint32_t& r3,
                                         uint32_t addr) {
    asm volatile("ldmatrix.sync.aligned.m8n8.x4.trans.shared.b16 {%0,%1,%2,%3}, [%4];"
                 : "=r"(r0), "=r"(r1), "=r"(r2), "=r"(r3) : "r"(addr));
}
__device__ __forceinline__ void mma16816h(float* c, const uint32_t* a, const uint32_t* b) {
    asm volatile(
        "mma.sync.aligned.m16n8k16.row.col.f32.f16.f16.f32 "
        "{%0,%1,%2,%3}, {%4,%5,%6,%7}, {%8,%9}, {%0,%1,%2,%3};"
        : "+f"(c[0]), "+f"(c[1]), "+f"(c[2]), "+f"(c[3])
        : "r"(a[0]), "r"(a[1]), "r"(a[2]), "r"(a[3]), "r"(b[0]), "r"(b[1]));
}
__device__ __forceinline__ uint32_t packh2(float a, float b) {
    __half2 h = __floats2half2_rn(a, b);
    return *(uint32_t*)&h;
}

// ---------------------------------------------------------------------------
// combined fp32->fp16 quantization: y=0 -> x (n=NX4), y=1..4 -> W_{y-1} (n=NW4)
// ---------------------------------------------------------------------------
__global__ void quant_all_kernel(const float* __restrict__ x,
                                 const float* __restrict__ w0, const float* __restrict__ w1,
                                 const float* __restrict__ w2, const float* __restrict__ w3,
                                 __half* __restrict__ dx, __half* __restrict__ dw,
                                 int nx4, int nw4)
{
    int i = blockIdx.x * blockDim.x + threadIdx.x;
    const int y = blockIdx.y;
    const float* src;
    __half* dst;
    int n4;
    if (y == 0) { src = x; dst = dx; n4 = nx4; }
    else {
        src = (y == 1) ? w0 : (y == 2) ? w1 : (y == 3) ? w2 : w3;
        dst = dw + (size_t)(y - 1) * DM * DM;
        n4 = nw4;
    }
    if (i < n4) {
        float4 v = *(const float4*)(src + i * 4);
        __half2 H0 = __floats2half2_rn(v.x, v.y);
        __half2 H1 = __floats2half2_rn(v.z, v.w);
        *(uint2*)(dst + i * 4) = make_uint2(*(uint32_t*)&H0, *(uint32_t*)&H1);
    }
}

// ---------------------------------------------------------------------------
// HMMA GEMM (fp16): C[m,n] = A[m,:]*W[n,:] + bias[n]
// BK=64 k-chunks, 3-stage cp.async ring, ONE barrier per chunk.
// SCATTER=1: fp16 scatter into [B,H,S,dk]; z==0 (Q) pre-scaled by 1/8.
// SCATTER=0: fp32 row-major [M,DM].
// ---------------------------------------------------------------------------
#define BKG    64
#define NCHK   (DM / BKG)         // 16
#define ROWB   144                // 64 fp16 (128B) + 16B pad
#define TILEB  (128 * ROWB)       // 18432
#define STAGEB (2 * TILEB)        // A, W  = 36864
#define NSTG   3
#define GSMEM  (NSTG * STAGEB)    // 110592

template<int SCATTER>
__global__ void __launch_bounds__(256) mma_gemm_kernel(
    const __half* __restrict__ A, const __half* __restrict__ W, int wbase,
    const float* __restrict__ b0, const float* __restrict__ b1, const float* __restrict__ b2,
    float* __restrict__ Cfp,
    __half* __restrict__ H0, __half* __restrict__ H1, __half* __restrict__ H2)
{
    extern __shared__ char sm[];
    const uint32_t sbase = smem_u32(sm);

    const int tid  = threadIdx.x;
    const int warp = tid >> 5;
    const int lane = tid & 31;

    const int z  = blockIdx.z;
    const float* bias = (z == 0) ? b0 : (z == 1) ? b1 : b2;
    __half* Hc = (z == 0) ? H0 : (z == 1) ? H1 : H2;
    const float oscale = (SCATTER && z == 0) ? 0.125f : 1.0f;
    const int m0 = blockIdx.x * 128;
    const int n0 = blockIdx.y * 128;

    const int warp_m = (warp & 1) * 64;
    const int warp_n = (warp >> 1) * 32;

    // loaders: tile = tid>>7 (0:A, 1:W), one 128B row per thread per chunk
    const int ltile = tid >> 7;
    const int lrow  = tid & 127;
    const __half* lsrc = ltile
        ? (W + (size_t)(wbase + z) * DM * DM + (size_t)(n0 + lrow) * DM)
        : (A + (size_t)(m0 + lrow) * DM);
    const uint32_t ldst0 = sbase + ltile * TILEB + lrow * ROWB;

    auto issue_stage = [&](int c) {
        const int s = c % NSTG;
        const int k0 = c * BKG;
        const uint32_t d = ldst0 + s * STAGEB;
        const char* p = (const char*)(lsrc + k0);
#pragma unroll
        for (int i = 0; i < 8; i++) cp16(d + i * 16, p + i * 16);
        cp_commit();
    };

    const uint32_t a_off = (uint32_t)(warp_m + (lane & 15)) * ROWB + ((lane >> 4) << 4);
    const uint32_t b_off = (uint32_t)(warp_n + ((lane & 16) >> 1) + (lane & 7)) * ROWB
                         + ((lane & 8) ? 16u : 0u);

    float acc[4][4][4];
#pragma unroll
    for (int i = 0; i < 4; i++)
#pragma unroll
        for (int j = 0; j < 4; j++)
#pragma unroll
            for (int r = 0; r < 4; r++) acc[i][j][r] = 0.f;

    issue_stage(0);
    issue_stage(1);

    for (int c = 0; c < NCHK; c++) {
        cp_wait_rem(NCHK - 1 - c >= 1 ? 1 : 0);
        __syncthreads();                      // all warps done with chunk c-1
        if (c + 2 < NCHK) issue_stage(c + 2); // overwrites stage (c-1)%3 — safe

        const uint32_t tA = sbase + (c % NSTG) * STAGEB;
        const uint32_t tW = tA + TILEB;

#pragma unroll
        for (int ks = 0; ks < 4; ks++) {
            const uint32_t ko = ks * 32;      // 16 fp16 = 32 bytes

            uint32_t bw[4][2];
#pragma unroll
            for (int bj = 0; bj < 2; bj++) {
                uint32_t r0, r1, r2, r3;
                ldsm_x4(r0, r1, r2, r3, tW + b_off + bj * (16 * ROWB) + ko);
                bw[bj*2+0][0] = r0; bw[bj*2+0][1] = r1;
                bw[bj*2+1][0] = r2; bw[bj*2+1][1] = r3;
            }

            uint32_t a[4][4];
#pragma unroll
            for (int mi = 0; mi < 4; mi++)
                ldsm_x4(a[mi][0], a[mi][1], a[mi][2], a[mi][3],
                        tA + a_off + mi * (16 * ROWB) + ko);
#pragma unroll
            for (int mi = 0; mi < 4; mi++)
#pragma unroll
                for (int nj = 0; nj < 4; nj++)
                    mma16816h(acc[mi][nj], a[mi], bw[nj]);
        }
    }

    const int g = lane >> 2;
    const int t = lane & 3;
#pragma unroll
    for (int mi = 0; mi < 4; mi++) {
#pragma unroll
        for (int nj = 0; nj < 4; nj++) {
            const int n  = n0 + warp_n + nj * 8 + t * 2;
            const float bx = __ldg(bias + n);
            const float by = __ldg(bias + n + 1);
#pragma unroll
            for (int half = 0; half < 2; half++) {
                const int m = m0 + warp_m + mi * 16 + g + half * 8;
                float vx = acc[mi][nj][half * 2 + 0] + bx;
                float vy = acc[mi][nj][half * 2 + 1] + by;
                if (SCATTER) {
                    const int bidx = m >> 11;
                    const int sidx = m & 2047;
                    const int hh   = n >> 6;
                    const int dc   = n & 63;
                    const size_t idx = ((size_t)((bidx * NH + hh) * SS + sidx) << 6) + dc;
                    *(uint32_t*)&Hc[idx] = packh2(vx * oscale, vy * oscale);
                } else {
                    *(float2*)&Cfp[(size_t)m * DM + n] = make_float2(vx, vy);
                }
            }
        }
    }
}

// ---------------------------------------------------------------------------
// HMMA flash attention, 4-stage K/V ring, one barrier per chunk,
// fast-path for fully unmasked chunks. Q pre-scaled by 1/8.
// ---------------------------------------------------------------------------
#define ROWAB  144
#define TILEA  (64 * ROWAB)
#define STAGEA (2 * TILEA + 256)
#define ANSTG  4
#define ASMEM  (ANSTG * STAGEA)   // 74752

__global__ void __launch_bounds__(256) mma_flash_kernel(const int* __restrict__ pad)
{
    extern __shared__ char sm[];
    const uint32_t sbase = smem_u32(sm);

    const int tid  = threadIdx.x;
    const int warp = tid >> 5;
    const int lane = tid & 31;
    const int g = lane >> 2;
    const int t = lane & 3;

    const int bh = blockIdx.x;
    const int qt = 15 - blockIdx.y;          // heavy tiles first
    const int b  = bh >> 4;
    const int h  = bh & 15;
    const int q0 = qt * 128;

    const size_t bhoff = (size_t)bh * SS * DKH;
    const __half* Qq = g_q + bhoff;
    const __half* Kq = g_k + bhoff;
    const __half* Vq = g_v + bhoff;

    // ---- stage Q into stage-0 region ----
    {
        const int row = tid >> 1;
        const int hlf = tid & 1;
        const __half* src = Qq + (size_t)(q0 + row) * DKH + hlf * 32;
        const uint32_t dst = sbase + (row >> 6) * TILEA + (row & 63) * ROWAB + hlf * 64;
#pragma unroll
        for (int i = 0; i < 4; i++) cp16(dst + i * 16, (const char*)src + i * 16);
    }
    cp_commit();
    cp_wait<0>();
    __syncthreads();

    uint32_t qh[4][4];
    {
        const int wrow = warp * 16 + (lane & 15);
        const uint32_t qb = sbase + (wrow >> 6) * TILEA + (wrow & 63) * ROWAB + ((lane >> 4) << 4);
#pragma unroll
        for (int kc = 0; kc < 4; kc++)
            ldsm_x4(qh[kc][0], qh[kc][1], qh[kc][2], qh[kc][3], qb + kc * 32);
    }
    __syncthreads();   // Q consumed; ring reusable

    float oacc[8][4];
#pragma unroll
    for (int j = 0; j < 8; j++)
#pragma unroll
        for (int r = 0; r < 4; r++) oacc[j][r] = 0.f;
    float mA = -1e30f, mB = -1e30f, lA = 0.f, lB = 0.f;

    const int cmax = 2 * qt + 1;
    const int qrA = q0 + warp * 16 + g;
    const int qrB = qrA + 8;
    const int wmin = q0 + warp * 16;

    auto issue = [&](int c) {
        const int stg = c & (ANSTG - 1);
        const int tile = tid >> 7;
        const int rjob = tid & 127;
        const int row  = rjob >> 1;
        const int hlf  = rjob & 1;
        const __half* src = (tile ? Vq : Kq) + (size_t)(c * 64 + row) * DKH + hlf * 32;
        const uint32_t dst = sbase + stg * STAGEA + tile * TILEA + row * ROWAB + hlf * 64;
#pragma unroll
        for (int i = 0; i < 4; i++) cp16(dst + i * 16, (const char*)src + i * 16);
        if (tid < 16)
            cp16(sbase + stg * STAGEA + 2 * TILEA + tid * 16,
                 (const char*)(pad + b * SS + c * 64) + tid * 16);
        cp_commit();
    };

    issue(0);
    if (cmax >= 1) issue(1);
    if (cmax >= 2) issue(2);

    for (int c = 0; c <= cmax; c++) {
        cp_wait_rem(cmax - c);
        __syncthreads();                    // all warps done with chunk c-1
        if (c + 3 <= cmax) issue(c + 3);

        const uint32_t st = sbase + (c & (ANSTG - 1)) * STAGEA;
        const int* padsm = (const int*)(sm + (size_t)(c & (ANSTG - 1)) * STAGEA + 2 * TILEA);
        const int kc0 = c * 64;

        // ---- S = Q K^T ----
        float sacc[8][4];
#pragma unroll
        for (int j = 0; j < 8; j++)
#pragma unroll
            for (int r = 0; r < 4; r++) sacc[j][r] = 0.f;

#pragma unroll
        for (int p = 0; p < 4; p++) {
            const uint32_t kb = st + (uint32_t)(p * 16 + ((lane & 16) >> 1) + (lane & 7)) * ROWAB
                              + ((lane & 8) ? 16u : 0u);
#pragma unroll
            for (int kc = 0; kc < 4; kc++) {
                uint32_t k0, k1, k2, k3;
                ldsm_x4(k0, k1, k2, k3, kb + kc * 32);
                uint32_t bk0[2] = {k0, k1}, bk1[2] = {k2, k3};
                mma16816h(sacc[2*p+0], qh[kc], bk0);
                mma16816h(sacc[2*p+1], qh[kc], bk1);
            }
        }

        // ---- pad detection (warp-uniform) ----
        const int padv = padsm[2 * lane] | padsm[2 * lane + 1];
        const bool anypad = __ballot_sync(0xffffffffu, padv != 0) != 0u;
        const bool fast = (kc0 + 63 <= wmin) && !anypad;

        float rmA = -1e30f, rmB = -1e30f;
        if (fast) {
#pragma unroll
            for (int j = 0; j < 8; j++) {
                rmA = fmaxf(rmA, fmaxf(sacc[j][0], sacc[j][1]));
                rmB = fmaxf(rmB, fmaxf(sacc[j][2], sacc[j][3]));
            }
        } else {
#pragma unroll
            for (int j = 0; j < 8; j++) {
                const int k0i = kc0 + j * 8 + t * 2;
                const bool pm0 = padsm[j * 8 + t * 2]     != 0;
                const bool pm1 = padsm[j * 8 + t * 2 + 1] != 0;
                float s0 = sacc[j][0]; if (k0i     > qrA || pm0) s0 = -1e30f;
                float s1 = sacc[j][1]; if (k0i + 1 > qrA || pm1) s1 = -1e30f;
                float s2 = sacc[j][2]; if (k0i     > qrB || pm0) s2 = -1e30f;
                float s3 = sacc[j][3]; if (k0i + 1 > qrB || pm1) s3 = -1e30f;
                sacc[j][0] = s0; sacc[j][1] = s1; sacc[j][2] = s2; sacc[j][3] = s3;
                rmA = fmaxf(rmA, fmaxf(s0, s1));
                rmB = fmaxf(rmB, fmaxf(s2, s3));
            }
        }
#pragma unroll
        for (int o = 1; o <= 2; o <<= 1) {
            rmA = fmaxf(rmA, __shfl_xor_sync(0xffffffffu, rmA, o));
            rmB = fmaxf(rmB, __shfl_xor_sync(0xffffffffu, rmB, o));
        }
        const float mnA = fmaxf(mA, rmA);
        const float mnB = fmaxf(mB, rmB);
        const float aAl = __expf(mA - mnA);
        const float aBl = __expf(mB - mnB);
        mA = mnA; mB = mnB;

        float sumA = 0.f, sumB = 0.f;
        if (fast) {
#pragma unroll
            for (int j = 0; j < 8; j++) {
                float p0 = __expf(sacc[j][0] - mnA);
                float p1 = __expf(sacc[j][1] - mnA);
                float p2 = __expf(sacc[j][2] - mnB);
                float p3 = __expf(sacc[j][3] - mnB);
                sumA += p0 + p1; sumB += p2 + p3;
                sacc[j][0] = p0; sacc[j][1] = p1; sacc[j][2] = p2; sacc[j][3] = p3;
            }
        } else {
#pragma unroll
            for (int j = 0; j < 8; j++) {
                float p0 = (sacc[j][0] <= -1e30f) ? 0.f : __expf(sacc[j][0] - mnA);
                float p1 = (sacc[j][1] <= -1e30f) ? 0.f : __expf(sacc[j][1] - mnA);
                float p2 = (sacc[j][2] <= -1e30f) ? 0.f : __expf(sacc[j][2] - mnB);
                float p3 = (sacc[j][3] <= -1e30f) ? 0.f : __expf(sacc[j][3] - mnB);
                sumA += p0 + p1; sumB += p2 + p3;
                sacc[j][0] = p0; sacc[j][1] = p1; sacc[j][2] = p2; sacc[j][3] = p3;
            }
        }
#pragma unroll
        for (int o = 1; o <= 2; o <<= 1) {
            sumA += __shfl_xor_sync(0xffffffffu, sumA, o);
            sumB += __shfl_xor_sync(0xffffffffu, sumB, o);
        }
        lA = lA * aAl + sumA;
        lB = lB * aBl + sumB;
#pragma unroll
        for (int j = 0; j < 8; j++) {
            oacc[j][0] *= aAl; oacc[j][1] *= aAl;
            oacc[j][2] *= aBl; oacc[j][3] *= aBl;
        }

        // ---- P -> fp16 A-frags ----
        uint32_t pah[4][4];
#pragma unroll
        for (int kc = 0; kc < 4; kc++) {
            const int j0 = 2 * kc, j1 = 2 * kc + 1;
            pah[kc][0] = packh2(sacc[j0][0], sacc[j0][1]);
            pah[kc][1] = packh2(sacc[j0][2], sacc[j0][3]);
            pah[kc][2] = packh2(sacc[j1][0], sacc[j1][1]);
            pah[kc][3] = packh2(sacc[j1][2], sacc[j1][3]);
        }

        // ---- O += P V ----
#pragma unroll
        for (int p = 0; p < 4; p++) {
#pragma unroll
            for (int kc = 0; kc < 4; kc++) {
                const uint32_t vb = st + TILEA
                                  + (uint32_t)(kc * 16 + (lane & 15)) * ROWAB
                                  + (uint32_t)(p * 32) + ((lane >> 4) << 4);
                uint32_t v0, v1, v2, v3;
                ldsm_x4t(v0, v1, v2, v3, vb);
                uint32_t bv0[2] = {v0, v1}, bv1[2] = {v2, v3};
                mma16816h(oacc[2*p+0], pah[kc], bv0);
                mma16816h(oacc[2*p+1], pah[kc], bv1);
            }
        }
    }

    // ---- epilogue ----
    const float invA = (lA > 0.f) ? (1.f / lA) : 0.f;
    const float invB = (lB > 0.f) ? (1.f / lB) : 0.f;
    const size_t rowA = (size_t)(b * SS + qrA) * DM + h * 64;
    const size_t rowB = (size_t)(b * SS + qrB) * DM + h * 64;
#pragma unroll
    for (int j = 0; j < 8; j++) {
        const int n = j * 8 + t * 2;
        *(uint32_t*)&g_ao[rowA + n] = packh2(oacc[j][0] * invA, oacc[j][1] * invA);
        *(uint32_t*)&g_ao[rowB + n] = packh2(oacc[j][2] * invB, oacc[j][3] * invB);
    }
}

// ---------------------------------------------------------------------------
extern "C" void kernel_launch(void* const* d_in, const int* in_sizes, int n_in,
                              void* d_out, int out_size)
{
    (void)in_sizes; (void)n_in; (void)out_size;
    const float* x   = (const float*)d_in[0];
    const int*   pad = (const int*)  d_in[1];
    const float* Wq  = (const float*)d_in[2];
    const float* bq  = (const float*)d_in[3];
    const float* Wk  = (const float*)d_in[4];
    const float* bk  = (const float*)d_in[5];
    const float* Wv  = (const float*)d_in[6];
    const float* bv  = (const float*)d_in[7];
    const float* Wo  = (const float*)d_in[8];
    const float* bo  = (const float*)d_in[9];
    float* out = (float*)d_out;

    __half *x16, *w16, *q16, *k16, *v16, *ao16;
    cudaGetSymbolAddress((void**)&x16, g_x16);
    cudaGetSymbolAddress((void**)&w16, g_w);
    cudaGetSymbolAddress((void**)&q16, g_q);
    cudaGetSymbolAddress((void**)&k16, g_k);
    cudaGetSymbolAddress((void**)&v16, g_v);
    cudaGetSymbolAddress((void**)&ao16, g_ao);

    cudaFuncSetAttribute(mma_gemm_kernel<1>,
                         cudaFuncAttributeMaxDynamicSharedMemorySize, GSMEM);
    cudaFuncSetAttribute(mma_gemm_kernel<0>,
                         cudaFuncAttributeMaxDynamicSharedMemorySize, GSMEM);
    cudaFuncSetAttribute(mma_flash_kernel,
                         cudaFuncAttributeMaxDynamicSharedMemorySize, ASMEM);

    const int NX4 = MROWS * DM / 4;
    const int NW4 = DM * DM / 4;

    // 1) fp16 quantization of x + all weights, single launch
    quant_all_kernel<<<dim3((NX4 + 255) / 256, 5), 256>>>(
        x, Wq, Wk, Wv, Wo, x16, w16, NX4, NW4);

    // 2) QKV projection -> fp16 [B,H,S,dk]  (Q pre-scaled by 1/8)
    mma_gemm_kernel<1><<<dim3(MROWS/128, DM/128, 3), 256, GSMEM>>>(
        x16, w16, 0, bq, bk, bv, nullptr, q16, k16, v16);

    // 3) HMMA flash attention -> fp16 [B,S,DM]
    mma_flash_kernel<<<dim3(BB*NH, SS/128), 256, ASMEM>>>(pad);

    // 4) output projection -> d_out (fp32)
    mma_gemm_kernel<0><<<dim3(MROWS/128, DM/128, 1), 256, GSMEM>>>(
        ao16, w16, 3, bo, bo, bo, out, nullptr, nullptr, nullptr);
}

// round 17
// speedup vs baseline: 1.2482x; 1.2482x over previous
#include <cuda_runtime.h>
#include <cuda_fp16.h>
#include <cstdint>

#define DM   1024
#define NH   16
#define DKH  64
#define BB   4
#define SS   2048
#define MROWS (BB*SS)   // 8192

// ---------------- device scratch (allocation-free rule) ----------------
__device__ __half g_x16[MROWS*DM];
__device__ __half g_w[4*DM*DM];
__device__ __half g_q[BB*NH*SS*DKH];   // pre-scaled by 1/8
__device__ __half g_k[BB*NH*SS*DKH];
__device__ __half g_v[BB*NH*SS*DKH];
__device__ __half g_ao[MROWS*DM];

// ---------------- PTX helpers (baseline ISA: sm_80-class) ----------------
__device__ __forceinline__ uint32_t smem_u32(const void* p) {
    uint32_t a;
    asm("{ .reg .u64 t; cvta.to.shared.u64 t, %1; cvt.u32.u64 %0, t; }" : "=r"(a) : "l"(p));
    return a;
}
__device__ __forceinline__ void cp16(uint32_t dst, const void* src) {
    asm volatile("cp.async.cg.shared.global [%0], [%1], 16;" :: "r"(dst), "l"(src));
}
__device__ __forceinline__ void cp_commit() {
    asm volatile("cp.async.commit_group;" ::: "memory");
}
template<int N> __device__ __forceinline__ void cp_wait() {
    asm volatile("cp.async.wait_group %0;" :: "n"(N) : "memory");
}
__device__ __forceinline__ void cp_wait_rem(int rem) {
    if (rem >= 2)      cp_wait<2>();
    else if (rem == 1) cp_wait<1>();
    else               cp_wait<0>();
}
__device__ __forceinline__ void ldsm_x4(uint32_t& r0, uint32_t& r1, uint32_t& r2, uint32_t& r3,
                                        uint32_t addr) {
    asm volatile("ldmatrix.sync.aligned.m8n8.x4.shared.b16 {%0,%1,%2,%3}, [%4];"
                 : "=r"(r0), "=r"(r1), "=r"(r2), "=r"(r3) : "r"(addr));
}
__device__ __forceinline__ void ldsm_x4t(uint32_t& r0, uint32_t& r1, uint32_t& r2, uint32_t& r3,
                                         uint32_t addr) {
    asm volatile("ldmatrix.sync.aligned.m8n8.x4.trans.shared.b16 {%0,%1,%2,%3}, [%4];"
                 : "=r"(r0), "=r"(r1), "=r"(r2), "=r"(r3) : "r"(addr));
}
__device__ __forceinline__ void mma16816h(float* c, const uint32_t* a, const uint32_t* b) {
    asm volatile(
        "mma.sync.aligned.m16n8k16.row.col.f32.f16.f16.f32 "
        "{%0,%1,%2,%3}, {%4,%5,%6,%7}, {%8,%9}, {%0,%1,%2,%3};"
        : "+f"(c[0]), "+f"(c[1]), "+f"(c[2]), "+f"(c[3])
        : "r"(a[0]), "r"(a[1]), "r"(a[2]), "r"(a[3]), "r"(b[0]), "r"(b[1]));
}
__device__ __forceinline__ uint32_t packh2(float a, float b) {
    __half2 h = __floats2half2_rn(a, b);
    return *(uint32_t*)&h;
}

// ---------------------------------------------------------------------------
// combined fp32->fp16 quantization: y=0 -> x (n=NX4), y=1..4 -> W_{y-1} (n=NW4)
// ---------------------------------------------------------------------------
__global__ void quant_all_kernel(const float* __restrict__ x,
                                 const float* __restrict__ w0, const float* __restrict__ w1,
                                 const float* __restrict__ w2, const float* __restrict__ w3,
                                 __half* __restrict__ dx, __half* __restrict__ dw,
                                 int nx4, int nw4)
{
    int i = blockIdx.x * blockDim.x + threadIdx.x;
    const int y = blockIdx.y;
    const float* src;
    __half* dst;
    int n4;
    if (y == 0) { src = x; dst = dx; n4 = nx4; }
    else {
        src = (y == 1) ? w0 : (y == 2) ? w1 : (y == 3) ? w2 : w3;
        dst = dw + (size_t)(y - 1) * DM * DM;
        n4 = nw4;
    }
    if (i < n4) {
        float4 v = *(const float4*)(src + i * 4);
        __half2 H0 = __floats2half2_rn(v.x, v.y);
        __half2 H1 = __floats2half2_rn(v.z, v.w);
        *(uint2*)(dst + i * 4) = make_uint2(*(uint32_t*)&H0, *(uint32_t*)&H1);
    }
}

// ---------------------------------------------------------------------------
// HMMA GEMM (fp16): C[m,n] = A[m,:]*W[n,:] + bias[n]
// CTA tile 128x256, warp tile 64x64 (8 warps, 2m x 4n), BK=32, 3-stage ring.
// SCATTER=1: fp16 scatter into [B,H,S,dk]; z==0 (Q) pre-scaled by 1/8.
// SCATTER=0: fp32 row-major [M,DM].
// ---------------------------------------------------------------------------
#define BKG    32
#define NCHK   (DM / BKG)         // 32
#define ROWB   80                 // 32 fp16 (64B) + 16B pad
#define WOFFB  (128 * ROWB)       // W tile starts after 128 A rows = 10240
#define STAGEB (384 * ROWB)       // A(128) + W(256) rows = 30720
#define NSTG   3
#define GSMEM  (NSTG * STAGEB)    // 92160

template<int SCATTER>
__global__ void __launch_bounds__(256) mma_gemm_kernel(
    const __half* __restrict__ A, const __half* __restrict__ W, int wbase,
    const float* __restrict__ b0, const float* __restrict__ b1, const float* __restrict__ b2,
    float* __restrict__ Cfp,
    __half* __restrict__ H0, __half* __restrict__ H1, __half* __restrict__ H2)
{
    extern __shared__ char sm[];
    const uint32_t sbase = smem_u32(sm);

    const int tid  = threadIdx.x;
    const int warp = tid >> 5;
    const int lane = tid & 31;

    const int z  = blockIdx.z;
    const float* bias = (z == 0) ? b0 : (z == 1) ? b1 : b2;
    __half* Hc = (z == 0) ? H0 : (z == 1) ? H1 : H2;
    const float oscale = (SCATTER && z == 0) ? 0.125f : 1.0f;
    const int m0 = blockIdx.x * 128;
    const int n0 = blockIdx.y * 256;

    const int warp_m = (warp & 1) * 64;
    const int warp_n = (warp >> 1) * 64;

    // ---- loader: 1536 cp16 jobs per chunk (A 512, W 1024); 6 per thread ----
    const __half* Wsel = W + (size_t)(wbase + z) * DM * DM;
    const char* lsrc[6];
    uint32_t    loff[6];
#pragma unroll
    for (int i = 0; i < 6; i++) {
        const int j = tid + i * 256;
        if (j < 512) {
            const int r = j >> 2, seg = j & 3;
            lsrc[i] = (const char*)(A + (size_t)(m0 + r) * DM) + seg * 16;
            loff[i] = (uint32_t)(r * ROWB + seg * 16);
        } else {
            const int jj = j - 512;
            const int r = jj >> 2, seg = jj & 3;
            lsrc[i] = (const char*)(Wsel + (size_t)(n0 + r) * DM) + seg * 16;
            loff[i] = (uint32_t)(WOFFB + r * ROWB + seg * 16);
        }
    }

    auto issue_stage = [&](int c) {
        const int s = c % NSTG;
        const uint32_t d = sbase + s * STAGEB;
        const int kb = c * BKG * 2;          // byte offset along k
#pragma unroll
        for (int i = 0; i < 6; i++)
            cp16(d + loff[i], lsrc[i] + kb);
        cp_commit();
    };

    const uint32_t a_off = (uint32_t)(warp_m + (lane & 15)) * ROWB + ((lane >> 4) << 4);
    const uint32_t b_off = (uint32_t)WOFFB
                         + (uint32_t)(warp_n + ((lane & 16) >> 1) + (lane & 7)) * ROWB
                         + ((lane & 8) ? 16u : 0u);

    float acc[4][8][4];
#pragma unroll
    for (int i = 0; i < 4; i++)
#pragma unroll
        for (int j = 0; j < 8; j++)
#pragma unroll
            for (int r = 0; r < 4; r++) acc[i][j][r] = 0.f;

    issue_stage(0);
    issue_stage(1);

    for (int c = 0; c < NCHK; c++) {
        cp_wait_rem((NCHK - 1 - c >= 1) ? 1 : 0);
        __syncthreads();                      // all warps done with chunk c-1
        if (c + 2 < NCHK) issue_stage(c + 2); // overwrites stage (c-1)%3 — safe

        const uint32_t st = sbase + (c % NSTG) * STAGEB;

#pragma unroll
        for (int ks = 0; ks < 2; ks++) {
            const uint32_t ko = ks * 32;      // 16 fp16 = 32 bytes

            uint32_t bw[8][2];
#pragma unroll
            for (int bj = 0; bj < 4; bj++) {
                uint32_t r0, r1, r2, r3;
                ldsm_x4(r0, r1, r2, r3, st + b_off + bj * (16 * ROWB) + ko);
                bw[bj*2+0][0] = r0; bw[bj*2+0][1] = r1;
                bw[bj*2+1][0] = r2; bw[bj*2+1][1] = r3;
            }

            uint32_t a[4][4];
#pragma unroll
            for (int mi = 0; mi < 4; mi++)
                ldsm_x4(a[mi][0], a[mi][1], a[mi][2], a[mi][3],
                        st + a_off + mi * (16 * ROWB) + ko);
#pragma unroll
            for (int mi = 0; mi < 4; mi++)
#pragma unroll
                for (int nj = 0; nj < 8; nj++)
                    mma16816h(acc[mi][nj], a[mi], bw[nj]);
        }
    }

    const int g = lane >> 2;
    const int t = lane & 3;
#pragma unroll
    for (int mi = 0; mi < 4; mi++) {
#pragma unroll
        for (int nj = 0; nj < 8; nj++) {
            const int n  = n0 + warp_n + nj * 8 + t * 2;
            const float bx = __ldg(bias + n);
            const float by = __ldg(bias + n + 1);
#pragma unroll
            for (int half = 0; half < 2; half++) {
                const int m = m0 + warp_m + mi * 16 + g + half * 8;
                float vx = acc[mi][nj][half * 2 + 0] + bx;
                float vy = acc[mi][nj][half * 2 + 1] + by;
                if (SCATTER) {
                    const int bidx = m >> 11;
                    const int sidx = m & 2047;
                    const int hh   = n >> 6;
                    const int dc   = n & 63;
                    const size_t idx = ((size_t)((bidx * NH + hh) * SS + sidx) << 6) + dc;
                    *(uint32_t*)&Hc[idx] = packh2(vx * oscale, vy * oscale);
                } else {
                    *(float2*)&Cfp[(size_t)m * DM + n] = make_float2(vx, vy);
                }
            }
        }
    }
}

// ---------------------------------------------------------------------------
// HMMA flash attention, 4-stage K/V ring, one barrier per chunk,
// fast-path for fully unmasked chunks. Q pre-scaled by 1/8.  (unchanged)
// ---------------------------------------------------------------------------
#define ROWAB  144
#define TILEA  (64 * ROWAB)
#define STAGEA (2 * TILEA + 256)
#define ANSTG  4
#define ASMEM  (ANSTG * STAGEA)   // 74752

__global__ void __launch_bounds__(256) mma_flash_kernel(const int* __restrict__ pad)
{
    extern __shared__ char sm[];
    const uint32_t sbase = smem_u32(sm);

    const int tid  = threadIdx.x;
    const int warp = tid >> 5;
    const int lane = tid & 31;
    const int g = lane >> 2;
    const int t = lane & 3;

    const int bh = blockIdx.x;
    const int qt = 15 - blockIdx.y;          // heavy tiles first
    const int b  = bh >> 4;
    const int h  = bh & 15;
    const int q0 = qt * 128;

    const size_t bhoff = (size_t)bh * SS * DKH;
    const __half* Qq = g_q + bhoff;
    const __half* Kq = g_k + bhoff;
    const __half* Vq = g_v + bhoff;

    // ---- stage Q into stage-0 region ----
    {
        const int row = tid >> 1;
        const int hlf = tid & 1;
        const __half* src = Qq + (size_t)(q0 + row) * DKH + hlf * 32;
        const uint32_t dst = sbase + (row >> 6) * TILEA + (row & 63) * ROWAB + hlf * 64;
#pragma unroll
        for (int i = 0; i < 4; i++) cp16(dst + i * 16, (const char*)src + i * 16);
    }
    cp_commit();
    cp_wait<0>();
    __syncthreads();

    uint32_t qh[4][4];
    {
        const int wrow = warp * 16 + (lane & 15);
        const uint32_t qb = sbase + (wrow >> 6) * TILEA + (wrow & 63) * ROWAB + ((lane >> 4) << 4);
#pragma unroll
        for (int kc = 0; kc < 4; kc++)
            ldsm_x4(qh[kc][0], qh[kc][1], qh[kc][2], qh[kc][3], qb + kc * 32);
    }
    __syncthreads();   // Q consumed; ring reusable

    float oacc[8][4];
#pragma unroll
    for (int j = 0; j < 8; j++)
#pragma unroll
        for (int r = 0; r < 4; r++) oacc[j][r] = 0.f;
    float mA = -1e30f, mB = -1e30f, lA = 0.f, lB = 0.f;

    const int cmax = 2 * qt + 1;
    const int qrA = q0 + warp * 16 + g;
    const int qrB = qrA + 8;
    const int wmin = q0 + warp * 16;

    auto issue = [&](int c) {
        const int stg = c & (ANSTG - 1);
        const int tile = tid >> 7;
        const int rjob = tid & 127;
        const int row  = rjob >> 1;
        const int hlf  = rjob & 1;
        const __half* src = (tile ? Vq : Kq) + (size_t)(c * 64 + row) * DKH + hlf * 32;
        const uint32_t dst = sbase + stg * STAGEA + tile * TILEA + row * ROWAB + hlf * 64;
#pragma unroll
        for (int i = 0; i < 4; i++) cp16(dst + i * 16, (const char*)src + i * 16);
        if (tid < 16)
            cp16(sbase + stg * STAGEA + 2 * TILEA + tid * 16,
                 (const char*)(pad + b * SS + c * 64) + tid * 16);
        cp_commit();
    };

    issue(0);
    if (cmax >= 1) issue(1);
    if (cmax >= 2) issue(2);

    for (int c = 0; c <= cmax; c++) {
        cp_wait_rem(cmax - c);
        __syncthreads();                    // all warps done with chunk c-1
        if (c + 3 <= cmax) issue(c + 3);

        const uint32_t st = sbase + (c & (ANSTG - 1)) * STAGEA;
        const int* padsm = (const int*)(sm + (size_t)(c & (ANSTG - 1)) * STAGEA + 2 * TILEA);
        const int kc0 = c * 64;

        // ---- S = Q K^T ----
        float sacc[8][4];
#pragma unroll
        for (int j = 0; j < 8; j++)
#pragma unroll
            for (int r = 0; r < 4; r++) sacc[j][r] = 0.f;

#pragma unroll
        for (int p = 0; p < 4; p++) {
            const uint32_t kb = st + (uint32_t)(p * 16 + ((lane & 16) >> 1) + (lane & 7)) * ROWAB
                              + ((lane & 8) ? 16u : 0u);
#pragma unroll
            for (int kc = 0; kc < 4; kc++) {
                uint32_t k0, k1, k2, k3;
                ldsm_x4(k0, k1, k2, k3, kb + kc * 32);
                uint32_t bk0[2] = {k0, k1}, bk1[2] = {k2, k3};
                mma16816h(sacc[2*p+0], qh[kc], bk0);
                mma16816h(sacc[2*p+1], qh[kc], bk1);
            }
        }

        // ---- pad detection (warp-uniform) ----
        const int padv = padsm[2 * lane] | padsm[2 * lane + 1];
        const bool anypad = __ballot_sync(0xffffffffu, padv != 0) != 0u;
        const bool fast = (kc0 + 63 <= wmin) && !anypad;

        float rmA = -1e30f, rmB = -1e30f;
        if (fast) {
#pragma unroll
            for (int j = 0; j < 8; j++) {
                rmA = fmaxf(rmA, fmaxf(sacc[j][0], sacc[j][1]));
                rmB = fmaxf(rmB, fmaxf(sacc[j][2], sacc[j][3]));
            }
        } else {
#pragma unroll
            for (int j = 0; j < 8; j++) {
                const int k0i = kc0 + j * 8 + t * 2;
                const bool pm0 = padsm[j * 8 + t * 2]     != 0;
                const bool pm1 = padsm[j * 8 + t * 2 + 1] != 0;
                float s0 = sacc[j][0]; if (k0i     > qrA || pm0) s0 = -1e30f;
                float s1 = sacc[j][1]; if (k0i + 1 > qrA || pm1) s1 = -1e30f;
                float s2 = sacc[j][2]; if (k0i     > qrB || pm0) s2 = -1e30f;
                float s3 = sacc[j][3]; if (k0i + 1 > qrB || pm1) s3 = -1e30f;
                sacc[j][0] = s0; sacc[j][1] = s1; sacc[j][2] = s2; sacc[j][3] = s3;
                rmA = fmaxf(rmA, fmaxf(s0, s1));
                rmB = fmaxf(rmB, fmaxf(s2, s3));
            }
        }
#pragma unroll
        for (int o = 1; o <= 2; o <<= 1) {
            rmA = fmaxf(rmA, __shfl_xor_sync(0xffffffffu, rmA, o));
            rmB = fmaxf(rmB, __shfl_xor_sync(0xffffffffu, rmB, o));
        }
        const float mnA = fmaxf(mA, rmA);
        const float mnB = fmaxf(mB, rmB);
        const float aAl = __expf(mA - mnA);
        const float aBl = __expf(mB - mnB);
        mA = mnA; mB = mnB;

        float sumA = 0.f, sumB = 0.f;
        if (fast) {
#pragma unroll
            for (int j = 0; j < 8; j++) {
                float p0 = __expf(sacc[j][0] - mnA);
                float p1 = __expf(sacc[j][1] - mnA);
                float p2 = __expf(sacc[j][2] - mnB);
                float p3 = __expf(sacc[j][3] - mnB);
                sumA += p0 + p1; sumB += p2 + p3;
                sacc[j][0] = p0; sacc[j][1] = p1; sacc[j][2] = p2; sacc[j][3] = p3;
            }
        } else {
#pragma unroll
            for (int j = 0; j < 8; j++) {
                float p0 = (sacc[j][0] <= -1e30f) ? 0.f : __expf(sacc[j][0] - mnA);
                float p1 = (sacc[j][1] <= -1e30f) ? 0.f : __expf(sacc[j][1] - mnA);
                float p2 = (sacc[j][2] <= -1e30f) ? 0.f : __expf(sacc[j][2] - mnB);
                float p3 = (sacc[j][3] <= -1e30f) ? 0.f : __expf(sacc[j][3] - mnB);
                sumA += p0 + p1; sumB += p2 + p3;
                sacc[j][0] = p0; sacc[j][1] = p1; sacc[j][2] = p2; sacc[j][3] = p3;
            }
        }
#pragma unroll
        for (int o = 1; o <= 2; o <<= 1) {
            sumA += __shfl_xor_sync(0xffffffffu, sumA, o);
            sumB += __shfl_xor_sync(0xffffffffu, sumB, o);
        }
        lA = lA * aAl + sumA;
        lB = lB * aBl + sumB;
#pragma unroll
        for (int j = 0; j < 8; j++) {
            oacc[j][0] *= aAl; oacc[j][1] *= aAl;
            oacc[j][2] *= aBl; oacc[j][3] *= aBl;
        }

        // ---- P -> fp16 A-frags ----
        uint32_t pah[4][4];
#pragma unroll
        for (int kc = 0; kc < 4; kc++) {
            const int j0 = 2 * kc, j1 = 2 * kc + 1;
            pah[kc][0] = packh2(sacc[j0][0], sacc[j0][1]);
            pah[kc][1] = packh2(sacc[j0][2], sacc[j0][3]);
            pah[kc][2] = packh2(sacc[j1][0], sacc[j1][1]);
            pah[kc][3] = packh2(sacc[j1][2], sacc[j1][3]);
        }

        // ---- O += P V ----
#pragma unroll
        for (int p = 0; p < 4; p++) {
#pragma unroll
            for (int kc = 0; kc < 4; kc++) {
                const uint32_t vb = st + TILEA
                                  + (uint32_t)(kc * 16 + (lane & 15)) * ROWAB
                                  + (uint32_t)(p * 32) + ((lane >> 4) << 4);
                uint32_t v0, v1, v2, v3;
                ldsm_x4t(v0, v1, v2, v3, vb);
                uint32_t bv0[2] = {v0, v1}, bv1[2] = {v2, v3};
                mma16816h(oacc[2*p+0], pah[kc], bv0);
                mma16816h(oacc[2*p+1], pah[kc], bv1);
            }
        }
    }

    // ---- epilogue ----
    const float invA = (lA > 0.f) ? (1.f / lA) : 0.f;
    const float invB = (lB > 0.f) ? (1.f / lB) : 0.f;
    const size_t rowA = (size_t)(b * SS + qrA) * DM + h * 64;
    const size_t rowB = (size_t)(b * SS + qrB) * DM + h * 64;
#pragma unroll
    for (int j = 0; j < 8; j++) {
        const int n = j * 8 + t * 2;
        *(uint32_t*)&g_ao[rowA + n] = packh2(oacc[j][0] * invA, oacc[j][1] * invA);
        *(uint32_t*)&g_ao[rowB + n] = packh2(oacc[j][2] * invB, oacc[j][3] * invB);
    }
}

// ---------------------------------------------------------------------------
extern "C" void kernel_launch(void* const* d_in, const int* in_sizes, int n_in,
                              void* d_out, int out_size)
{
    (void)in_sizes; (void)n_in; (void)out_size;
    const float* x   = (const float*)d_in[0];
    const int*   pad = (const int*)  d_in[1];
    const float* Wq  = (const float*)d_in[2];
    const float* bq  = (const float*)d_in[3];
    const float* Wk  = (const float*)d_in[4];
    const float* bk  = (const float*)d_in[5];
    const float* Wv  = (const float*)d_in[6];
    const float* bv  = (const float*)d_in[7];
    const float* Wo  = (const float*)d_in[8];
    const float* bo  = (const float*)d_in[9];
    float* out = (float*)d_out;

    __half *x16, *w16, *q16, *k16, *v16, *ao16;
    cudaGetSymbolAddress((void**)&x16, g_x16);
    cudaGetSymbolAddress((void**)&w16, g_w);
    cudaGetSymbolAddress((void**)&q16, g_q);
    cudaGetSymbolAddress((void**)&k16, g_k);
    cudaGetSymbolAddress((void**)&v16, g_v);
    cudaGetSymbolAddress((void**)&ao16, g_ao);

    cudaFuncSetAttribute(mma_gemm_kernel<1>,
                         cudaFuncAttributeMaxDynamicSharedMemorySize, GSMEM);
    cudaFuncSetAttribute(mma_gemm_kernel<0>,
                         cudaFuncAttributeMaxDynamicSharedMemorySize, GSMEM);
    cudaFuncSetAttribute(mma_flash_kernel,
                         cudaFuncAttributeMaxDynamicSharedMemorySize, ASMEM);

    const int NX4 = MROWS * DM / 4;
    const int NW4 = DM * DM / 4;

    // 1) fp16 quantization of x + all weights, single launch
    quant_all_kernel<<<dim3((NX4 + 255) / 256, 5), 256>>>(
        x, Wq, Wk, Wv, Wo, x16, w16, NX4, NW4);

    // 2) QKV projection -> fp16 [B,H,S,dk]  (Q pre-scaled by 1/8)
    mma_gemm_kernel<1><<<dim3(MROWS/128, DM/256, 3), 256, GSMEM>>>(
        x16, w16, 0, bq, bk, bv, nullptr, q16, k16, v16);

    // 3) HMMA flash attention -> fp16 [B,S,DM]
    mma_flash_kernel<<<dim3(BB*NH, SS/128), 256, ASMEM>>>(pad);

    // 4) output projection -> d_out (fp32)
    mma_gemm_kernel<0><<<dim3(MROWS/128, DM/256, 1), 256, GSMEM>>>(
        ao16, w16, 3, bo, bo, bo, out, nullptr, nullptr, nullptr);
}